// round 1
// baseline (speedup 1.0000x reference)
#include <cuda_runtime.h>
#include <math.h>

#define NMAX 100000
#define EMAX 1600000
#define GEMM_SMEM ((128*132 + 128*128) * 4)

// ---------------- scratch (static device globals; no allocations) ----------------
__device__ __align__(16) float g_feat[NMAX * 128];   // W-transformed features
__device__ __align__(16) float g_h[NMAX * 128];      // layer activations
__device__ float g_el[NMAX * 4];
__device__ float g_er[NMAX * 4];
__device__ int   g_rowptr[NMAX + 1];
__device__ int   g_cursor[NMAX];
__device__ int   g_cnt[NMAX];
__device__ int   g_col[EMAX];

// ---------------- CSR build ----------------
__global__ void count_kernel(const int* __restrict__ dst, int* __restrict__ cnt, int E) {
    int i = blockIdx.x * blockDim.x + threadIdx.x;
    if (i < E) atomicAdd(&cnt[dst[i]], 1);
}

__global__ void scan_kernel(const int* __restrict__ cnt, int* __restrict__ rowptr,
                            int* __restrict__ cursor, int n) {
    __shared__ int part[1024];
    int t = threadIdx.x;
    int CH = (n + 1023) >> 10;
    int base = t * CH;
    int s = 0;
    for (int j = 0; j < CH; j++) { int idx = base + j; if (idx < n) s += cnt[idx]; }
    part[t] = s;
    __syncthreads();
    for (int off = 1; off < 1024; off <<= 1) {
        int v = (t >= off) ? part[t - off] : 0;
        __syncthreads();
        part[t] += v;
        __syncthreads();
    }
    int run = (t == 0) ? 0 : part[t - 1];
    for (int j = 0; j < CH; j++) {
        int idx = base + j;
        if (idx < n) { rowptr[idx] = run; cursor[idx] = run; run += cnt[idx]; }
    }
    if (t == 1023) rowptr[n] = part[1023];
}

__global__ void scatter_kernel(const int* __restrict__ src, const int* __restrict__ dst,
                               int* __restrict__ cursor, int* __restrict__ col, int E) {
    int i = blockIdx.x * blockDim.x + threadIdx.x;
    if (i < E) {
        int p = atomicAdd(&cursor[dst[i]], 1);
        col[p] = src[i];
    }
}

// ---------------- GEMM: feat = h @ W, fused el/er attention dots ----------------
// block = 256 threads, 128 rows x 128 cols per block, 8x8 register microtile.
template <int H>
__global__ void __launch_bounds__(256) gemm_kernel(
    const float* __restrict__ in, const float* __restrict__ W,
    const float* __restrict__ al, const float* __restrict__ ar,
    float* __restrict__ feat, float* __restrict__ el, float* __restrict__ er, int n) {
    extern __shared__ float smem[];
    float* as = smem;              // [128][132]  A transposed: as[k][r]
    float* ws = smem + 128 * 132;  // [128][128]  W row-major:  ws[k][c]

    const int t = threadIdx.x;
    const int row0 = blockIdx.x * 128;

    // stage W
    {
        const float4* W4 = (const float4*)W;
        float4* ws4 = (float4*)ws;
        for (int i = t; i < 4096; i += 256) ws4[i] = W4[i];
    }
    // stage A transposed
    {
        int tr = t >> 1;
        int half = t & 1;
        int r = row0 + tr;
        if (r < n) {
            const float4* in4 = (const float4*)(in + (size_t)r * 128);
#pragma unroll
            for (int q = 0; q < 16; q++) {
                int k0 = half * 64 + q * 4;
                float4 v = in4[k0 >> 2];
                as[(k0 + 0) * 132 + tr] = v.x;
                as[(k0 + 1) * 132 + tr] = v.y;
                as[(k0 + 2) * 132 + tr] = v.z;
                as[(k0 + 3) * 132 + tr] = v.w;
            }
        } else {
#pragma unroll
            for (int q = 0; q < 16; q++) {
                int k0 = half * 64 + q * 4;
                as[(k0 + 0) * 132 + tr] = 0.f;
                as[(k0 + 1) * 132 + tr] = 0.f;
                as[(k0 + 2) * 132 + tr] = 0.f;
                as[(k0 + 3) * 132 + tr] = 0.f;
            }
        }
    }
    __syncthreads();

    const int tx = t & 15, ty = t >> 4;
    const int c0 = tx * 8, r0 = ty * 8;

    float acc[8][8];
#pragma unroll
    for (int i = 0; i < 8; i++)
#pragma unroll
        for (int j = 0; j < 8; j++) acc[i][j] = 0.f;

#pragma unroll 4
    for (int k = 0; k < 128; k++) {
        float av[8], wv[8];
        *(float4*)&av[0] = *(const float4*)(as + k * 132 + r0);
        *(float4*)&av[4] = *(const float4*)(as + k * 132 + r0 + 4);
        *(float4*)&wv[0] = *(const float4*)(ws + k * 128 + c0);
        *(float4*)&wv[4] = *(const float4*)(ws + k * 128 + c0 + 4);
#pragma unroll
        for (int i = 0; i < 8; i++)
#pragma unroll
            for (int j = 0; j < 8; j++) acc[i][j] = fmaf(av[i], wv[j], acc[i][j]);
    }

    // epilogue: store feat, compute per-head attention dots el/er
    float alv[8], arv[8];
    *(float4*)&alv[0] = *(const float4*)(al + c0);
    *(float4*)&alv[4] = *(const float4*)(al + c0 + 4);
    *(float4*)&arv[0] = *(const float4*)(ar + c0);
    *(float4*)&arv[4] = *(const float4*)(ar + c0 + 4);

    const int glanes = 16 / H;  // threads (tx) covering one head's columns
#pragma unroll
    for (int i = 0; i < 8; i++) {
        int r = row0 + r0 + i;
        float pel = 0.f, per = 0.f;
#pragma unroll
        for (int j = 0; j < 8; j++) {
            pel = fmaf(acc[i][j], alv[j], pel);
            per = fmaf(acc[i][j], arv[j], per);
        }
#pragma unroll
        for (int off = glanes >> 1; off > 0; off >>= 1) {
            pel += __shfl_xor_sync(0xffffffffu, pel, off);
            per += __shfl_xor_sync(0xffffffffu, per, off);
        }
        if (r < n) {
            float4* f4 = (float4*)(feat + (size_t)r * 128 + c0);
            f4[0] = make_float4(acc[i][0], acc[i][1], acc[i][2], acc[i][3]);
            f4[1] = make_float4(acc[i][4], acc[i][5], acc[i][6], acc[i][7]);
            if ((tx & (glanes - 1)) == 0) {
                int hh = tx / glanes;
                el[r * H + hh] = pel;
                er[r * H + hh] = per;
            }
        }
    }
}

// ---------------- aggregation: edge softmax + weighted gather-sum, warp per node ----
template <int H, bool LAST>
__global__ void __launch_bounds__(256) agg_kernel(
    const float* __restrict__ feat, const float* __restrict__ el, const float* __restrict__ er,
    const float* __restrict__ hin, float* __restrict__ hout,
    const int* __restrict__ rowptr, const int* __restrict__ col,
    const float* __restrict__ b, int n) {
    int gw = (blockIdx.x * blockDim.x + threadIdx.x) >> 5;
    if (gw >= n) return;
    int l = threadIdx.x & 31;
    const int EL = 32 / H;          // lanes per head group
    int hd = l / EL;                // head for this lane (matches col mapping 4l/D)
    int li = l & (EL - 1);

    float erv = er[gw * H + hd];
    int start = rowptr[gw], end = rowptr[gw + 1];

    // pass A: per-head max, edge-parallel across lanes of the head group
    float mx = -3.402823466e38f;
    for (int j = start + li; j < end; j += EL) {
        int s = col[j];
        float e = el[s * H + hd] + erv;
        e = e > 0.f ? e : 0.2f * e;
        mx = fmaxf(mx, e);
    }
#pragma unroll
    for (int off = EL >> 1; off > 0; off >>= 1)
        mx = fmaxf(mx, __shfl_xor_sync(0xffffffffu, mx, off));

    // pass B: acc = sum exp(e-mx)*feat[src], sw = sum exp(e-mx)
    const float4* f4 = (const float4*)feat;
    float4 acc = make_float4(0.f, 0.f, 0.f, 0.f);
    float sw = 0.f;
    int j = start;
    for (; j + 1 < end; j += 2) {
        int s0 = col[j], s1 = col[j + 1];
        float e0 = el[s0 * H + hd] + erv;
        float e1 = el[s1 * H + hd] + erv;
        float4 fa = f4[(size_t)s0 * 32 + l];
        float4 fb = f4[(size_t)s1 * 32 + l];
        e0 = e0 > 0.f ? e0 : 0.2f * e0;
        e1 = e1 > 0.f ? e1 : 0.2f * e1;
        float w0 = __expf(e0 - mx);
        float w1 = __expf(e1 - mx);
        sw += w0 + w1;
        acc.x = fmaf(w0, fa.x, acc.x); acc.x = fmaf(w1, fb.x, acc.x);
        acc.y = fmaf(w0, fa.y, acc.y); acc.y = fmaf(w1, fb.y, acc.y);
        acc.z = fmaf(w0, fa.z, acc.z); acc.z = fmaf(w1, fb.z, acc.z);
        acc.w = fmaf(w0, fa.w, acc.w); acc.w = fmaf(w1, fb.w, acc.w);
    }
    if (j < end) {
        int s0 = col[j];
        float e0 = el[s0 * H + hd] + erv;
        float4 fa = f4[(size_t)s0 * 32 + l];
        e0 = e0 > 0.f ? e0 : 0.2f * e0;
        float w0 = __expf(e0 - mx);
        sw += w0;
        acc.x = fmaf(w0, fa.x, acc.x);
        acc.y = fmaf(w0, fa.y, acc.y);
        acc.z = fmaf(w0, fa.z, acc.z);
        acc.w = fmaf(w0, fa.w, acc.w);
    }

    float inv = sw > 0.f ? 1.0f / sw : 0.f;
    float4 r4 = ((const float4*)hin)[(size_t)gw * 32 + l];
    float4 b4 = ((const float4*)b)[l];
    float4 o;
    o.x = fmaf(acc.x, inv, r4.x + b4.x);
    o.y = fmaf(acc.y, inv, r4.y + b4.y);
    o.z = fmaf(acc.z, inv, r4.z + b4.z);
    o.w = fmaf(acc.w, inv, r4.w + b4.w);
    if (!LAST) {
        o.x = o.x > 0.f ? o.x : expm1f(o.x);
        o.y = o.y > 0.f ? o.y : expm1f(o.y);
        o.z = o.z > 0.f ? o.z : expm1f(o.z);
        o.w = o.w > 0.f ? o.w : expm1f(o.w);
    }
    ((float4*)hout)[(size_t)gw * 32 + l] = o;
}

// ---------------- launch ----------------
extern "C" void kernel_launch(void* const* d_in, const int* in_sizes, int n_in,
                              void* d_out, int out_size) {
    const float* nf   = (const float*)d_in[0];
    const float* Ws   = (const float*)d_in[1];
    const float* bs   = (const float*)d_in[2];
    const float* al_h = (const float*)d_in[3];
    const float* ar_h = (const float*)d_in[4];
    const float* al_o = (const float*)d_in[5];
    const float* ar_o = (const float*)d_in[6];
    const int*   src  = (const int*)d_in[7];
    const int*   dst  = (const int*)d_in[8];

    int n = in_sizes[0] / 128;
    int E = in_sizes[7];

    void *p_feat, *p_h, *p_el, *p_er, *p_rp, *p_cur, *p_cnt, *p_col;
    cudaGetSymbolAddress(&p_feat, g_feat);
    cudaGetSymbolAddress(&p_h, g_h);
    cudaGetSymbolAddress(&p_el, g_el);
    cudaGetSymbolAddress(&p_er, g_er);
    cudaGetSymbolAddress(&p_rp, g_rowptr);
    cudaGetSymbolAddress(&p_cur, g_cursor);
    cudaGetSymbolAddress(&p_cnt, g_cnt);
    cudaGetSymbolAddress(&p_col, g_col);

    float* feat = (float*)p_feat;
    float* h    = (float*)p_h;
    float* el   = (float*)p_el;
    float* er   = (float*)p_er;
    int*   rp   = (int*)p_rp;
    int*   cur  = (int*)p_cur;
    int*   cnt  = (int*)p_cnt;
    int*   col  = (int*)p_col;

    cudaFuncSetAttribute(gemm_kernel<4>, cudaFuncAttributeMaxDynamicSharedMemorySize, GEMM_SMEM);
    cudaFuncSetAttribute(gemm_kernel<1>, cudaFuncAttributeMaxDynamicSharedMemorySize, GEMM_SMEM);

    // CSR by dst (graph is a launch input; rebuilt every call)
    cudaMemsetAsync(cnt, 0, (size_t)n * sizeof(int));
    count_kernel<<<(E + 255) / 256, 256>>>(dst, cnt, E);
    scan_kernel<<<1, 1024>>>(cnt, rp, cur, n);
    scatter_kernel<<<(E + 255) / 256, 256>>>(src, dst, cur, col, E);

    int gb = (n + 127) / 128;
    int ab = (n + 7) / 8;

    // layer 0 (input nf)
    gemm_kernel<4><<<gb, 256, GEMM_SMEM>>>(nf, Ws, al_h, ar_h, feat, el, er, n);
    agg_kernel<4, false><<<ab, 256>>>(feat, el, er, nf, h, rp, col, bs, n);
    // layers 1,2 (in-place h)
    for (int i = 1; i < 3; i++) {
        gemm_kernel<4><<<gb, 256, GEMM_SMEM>>>(h, Ws + (size_t)i * 16384, al_h + i * 128,
                                               ar_h + i * 128, feat, el, er, n);
        agg_kernel<4, false><<<ab, 256>>>(feat, el, er, h, h, rp, col, bs + i * 128, n);
    }
    // layer 3 (1 head) -> d_out
    gemm_kernel<1><<<gb, 256, GEMM_SMEM>>>(h, Ws + (size_t)3 * 16384, al_o, ar_o, feat, el, er, n);
    agg_kernel<1, true><<<ab, 256>>>(feat, el, er, h, (float*)d_out, rp, col, bs + 3 * 128, n);
}

// round 3
// speedup vs baseline: 1.1894x; 1.1894x over previous
#include <cuda_runtime.h>
#include <cuda_bf16.h>
#include <math.h>
#include <cstdint>

#define NMAX 100000
#define EMAX 1600000

// ======================= scratch (static device globals) =======================
__device__ __align__(16) float g_feat[NMAX * 128];
__device__ __align__(16) float g_h[NMAX * 128];
__device__ float g_el[NMAX * 4];
__device__ float g_er[NMAX * 4];
__device__ int   g_rowptr[NMAX + 1];
__device__ int   g_cursor[NMAX];
__device__ int   g_cnt[NMAX];
__device__ int   g_col[EMAX];
__device__ __align__(16) __nv_bfloat16 g_wt_hi[128 * 128];
__device__ __align__(16) __nv_bfloat16 g_wt_lo[128 * 128];

// ======================= helpers =======================
__device__ __forceinline__ uint32_t smem_u32(const void* p) {
    uint32_t a;
    asm("{ .reg .u64 t; cvta.to.shared.u64 t, %1; cvt.u32.u64 %0, t; }" : "=r"(a) : "l"(p));
    return a;
}

__device__ __forceinline__ void ldm_x4(uint32_t addr, uint32_t& r0, uint32_t& r1,
                                       uint32_t& r2, uint32_t& r3) {
    asm volatile("ldmatrix.sync.aligned.m8n8.x4.shared.b16 {%0,%1,%2,%3}, [%4];"
                 : "=r"(r0), "=r"(r1), "=r"(r2), "=r"(r3) : "r"(addr));
}

__device__ __forceinline__ void mma16816(float* c, const uint32_t* a, const uint32_t* b) {
    asm volatile("mma.sync.aligned.m16n8k16.row.col.f32.bf16.bf16.f32 "
                 "{%0,%1,%2,%3}, {%4,%5,%6,%7}, {%8,%9}, {%0,%1,%2,%3};"
                 : "+f"(c[0]), "+f"(c[1]), "+f"(c[2]), "+f"(c[3])
                 : "r"(a[0]), "r"(a[1]), "r"(a[2]), "r"(a[3]), "r"(b[0]), "r"(b[1]));
}

// ======================= CSR build =======================
__global__ void count_kernel(const int* __restrict__ dst, int* __restrict__ cnt, int E) {
    int i = blockIdx.x * blockDim.x + threadIdx.x;
    if (i < E) atomicAdd(&cnt[dst[i]], 1);
}

__global__ void scan_kernel(const int* __restrict__ cnt, int* __restrict__ rowptr,
                            int* __restrict__ cursor, int n) {
    __shared__ int part[1024];
    int t = threadIdx.x;
    int CH = (n + 1023) >> 10;
    int base = t * CH;
    int s = 0;
    for (int j = 0; j < CH; j++) { int idx = base + j; if (idx < n) s += cnt[idx]; }
    part[t] = s;
    __syncthreads();
    for (int off = 1; off < 1024; off <<= 1) {
        int v = (t >= off) ? part[t - off] : 0;
        __syncthreads();
        part[t] += v;
        __syncthreads();
    }
    int run = (t == 0) ? 0 : part[t - 1];
    for (int j = 0; j < CH; j++) {
        int idx = base + j;
        if (idx < n) { rowptr[idx] = run; cursor[idx] = run; run += cnt[idx]; }
    }
    if (t == 1023) rowptr[n] = part[1023];
}

__global__ void scatter_kernel(const int* __restrict__ src, const int* __restrict__ dst,
                               int* __restrict__ cursor, int* __restrict__ col, int E) {
    int i = blockIdx.x * blockDim.x + threadIdx.x;
    if (i < E) {
        int p = atomicAdd(&cursor[dst[i]], 1);
        col[p] = src[i];
    }
}

// =============== W transpose + bf16 split ===============
__global__ void wtrans_kernel(const float* __restrict__ W,
                              __nv_bfloat16* __restrict__ wt_hi,
                              __nv_bfloat16* __restrict__ wt_lo) {
    int idx = blockIdx.x * 256 + threadIdx.x;
    int k = idx >> 7, nn = idx & 127;
    float v = W[idx];                           // W[k][n]
    __nv_bfloat16 h = __float2bfloat16(v);
    float lo = v - __bfloat162float(h);
    wt_hi[nn * 128 + k] = h;                    // Wt[n][k]
    wt_lo[nn * 128 + k] = __float2bfloat16(lo);
}

// =============== mma.sync GEMM: feat = h @ W (bf16x3 split), fused el/er ===============
// block: 256 threads (8 warps: 4 row x 2 col), tile 128x128, K=128.
// smem: a_hi, a_lo, b_hi, b_lo each [128][136] bf16 (272B row stride -> ldmatrix conflict-free)
#define LDT 136                       // padded row length in bf16 elems
#define TILE_B (128 * LDT * 2)        // 34816 bytes per tile
#define OF_AHI 0
#define OF_ALO TILE_B
#define OF_BHI (2 * TILE_B)
#define OF_BLO (3 * TILE_B)
#define MMA_SMEM (4 * TILE_B)

template <int H>
__global__ void __launch_bounds__(256) mma_gemm_kernel(
    const float* __restrict__ in,
    const __nv_bfloat16* __restrict__ wt_hi, const __nv_bfloat16* __restrict__ wt_lo,
    const float* __restrict__ al, const float* __restrict__ ar,
    float* __restrict__ feat, float* __restrict__ el, float* __restrict__ er, int n) {
    extern __shared__ char sm[];
    const uint32_t sb = smem_u32(sm);
    const int t = threadIdx.x;
    const int row0 = blockIdx.x * 128;

    // ---- stage B = Wt hi/lo ----
    for (int idx = t; idx < 2048; idx += 256) {
        int r = idx >> 4, c = idx & 15;
        *(uint4*)(sm + OF_BHI + r * 272 + c * 16) = ((const uint4*)wt_hi)[idx];
        *(uint4*)(sm + OF_BLO + r * 272 + c * 16) = ((const uint4*)wt_lo)[idx];
    }
    // ---- stage A: fp32 -> (hi, lo) bf16 ----
    for (int idx = t; idx < 2048; idx += 256) {
        int r = idx >> 4, c = idx & 15;
        int grow = row0 + r;
        float xs[8];
        if (grow < n) {
            const float4* p = (const float4*)(in + (size_t)grow * 128 + c * 8);
            float4 v0 = p[0], v1 = p[1];
            xs[0] = v0.x; xs[1] = v0.y; xs[2] = v0.z; xs[3] = v0.w;
            xs[4] = v1.x; xs[5] = v1.y; xs[6] = v1.z; xs[7] = v1.w;
        } else {
#pragma unroll
            for (int j = 0; j < 8; j++) xs[j] = 0.f;
        }
        union { uint4 u; __nv_bfloat16 b[8]; } uh, ul;
#pragma unroll
        for (int j = 0; j < 8; j++) {
            __nv_bfloat16 hv = __float2bfloat16(xs[j]);
            uh.b[j] = hv;
            ul.b[j] = __float2bfloat16(xs[j] - __bfloat162float(hv));
        }
        *(uint4*)(sm + OF_AHI + r * 272 + c * 16) = uh.u;
        *(uint4*)(sm + OF_ALO + r * 272 + c * 16) = ul.u;
    }
    __syncthreads();

    const int l = t & 31, w = t >> 5;
    const int wr = w >> 1, wc = w & 1;     // warp tile: rows 32*wr, cols 64*wc

    // ldmatrix lane address components
    const uint32_t a_lane = (uint32_t)((l & 15) * 272 + ((l >= 16) ? 16 : 0));
    const uint32_t b_lane = (uint32_t)(((l & 7) + ((l >= 16) ? 8 : 0)) * 272 + (((l & 15) >= 8) ? 16 : 0));

    float acc[2][8][4];
#pragma unroll
    for (int mi = 0; mi < 2; mi++)
#pragma unroll
        for (int nj = 0; nj < 8; nj++)
#pragma unroll
            for (int q = 0; q < 4; q++) acc[mi][nj][q] = 0.f;

#pragma unroll
    for (int p = 0; p < 3; p++) {
        const uint32_t abase = sb + ((p == 2) ? OF_ALO : OF_AHI) + (uint32_t)(wr * 32) * 272 + a_lane;
        const uint32_t bbase = sb + ((p == 1) ? OF_BLO : OF_BHI) + (uint32_t)(wc * 64) * 272 + b_lane;
#pragma unroll
        for (int ks = 0; ks < 8; ks++) {
            uint32_t a[2][4];
            ldm_x4(abase + ks * 32,            a[0][0], a[0][1], a[0][2], a[0][3]);
            ldm_x4(abase + 16 * 272 + ks * 32, a[1][0], a[1][1], a[1][2], a[1][3]);
            uint32_t b[8][2];
#pragma unroll
            for (int njp = 0; njp < 4; njp++) {
                uint32_t r0, r1, r2, r3;
                ldm_x4(bbase + (uint32_t)(njp * 16) * 272 + ks * 32, r0, r1, r2, r3);
                b[2 * njp][0] = r0; b[2 * njp][1] = r1;
                b[2 * njp + 1][0] = r2; b[2 * njp + 1][1] = r3;
            }
#pragma unroll
            for (int mi = 0; mi < 2; mi++)
#pragma unroll
                for (int nj = 0; nj < 8; nj++) mma16816(acc[mi][nj], a[mi], b[nj]);
        }
    }

    __syncthreads();   // tiles dead; smem reused below for H==1 partials

    // ---- epilogue: store feat + fused attention dots ----
    float* elp = (float*)(sm + OF_BLO);            // [2][128] partials (H==1)
    float* erp = elp + 256;
    const int q = l >> 2, qq = l & 3;

#pragma unroll
    for (int mi = 0; mi < 2; mi++) {
#pragma unroll
        for (int rh = 0; rh < 2; rh++) {
            int lrow = wr * 32 + mi * 16 + rh * 8 + q;
            int row = row0 + lrow;
            float pel[2] = {0.f, 0.f}, per[2] = {0.f, 0.f};
#pragma unroll
            for (int nj = 0; nj < 8; nj++) {
                float v0 = acc[mi][nj][rh * 2 + 0];
                float v1 = acc[mi][nj][rh * 2 + 1];
                int colg = wc * 64 + nj * 8 + qq * 2;
                if (row < n)
                    *(float2*)(feat + (size_t)row * 128 + colg) = make_float2(v0, v1);
                int hseg = nj >> 2;
                pel[hseg] = fmaf(v0, __ldg(al + colg), pel[hseg]);
                pel[hseg] = fmaf(v1, __ldg(al + colg + 1), pel[hseg]);
                per[hseg] = fmaf(v0, __ldg(ar + colg), per[hseg]);
                per[hseg] = fmaf(v1, __ldg(ar + colg + 1), per[hseg]);
            }
#pragma unroll
            for (int hseg = 0; hseg < 2; hseg++) {
                pel[hseg] += __shfl_xor_sync(0xffffffffu, pel[hseg], 1);
                pel[hseg] += __shfl_xor_sync(0xffffffffu, pel[hseg], 2);
                per[hseg] += __shfl_xor_sync(0xffffffffu, per[hseg], 1);
                per[hseg] += __shfl_xor_sync(0xffffffffu, per[hseg], 2);
            }
            if (H == 4) {
                if (qq == 0 && row < n) {
                    el[row * 4 + wc * 2 + 0] = pel[0];
                    er[row * 4 + wc * 2 + 0] = per[0];
                    el[row * 4 + wc * 2 + 1] = pel[1];
                    er[row * 4 + wc * 2 + 1] = per[1];
                }
            } else {
                if (qq == 0) {
                    elp[wc * 128 + lrow] = pel[0] + pel[1];
                    erp[wc * 128 + lrow] = per[0] + per[1];
                }
            }
        }
    }
    if (H == 1) {
        __syncthreads();
        if (t < 128) {
            int row = row0 + t;
            if (row < n) {
                el[row] = elp[t] + elp[128 + t];
                er[row] = erp[t] + erp[128 + t];
            }
        }
    }
}

// =============== aggregation: edge softmax + weighted gather, warp/node ===============
template <int H, bool LAST>
__global__ void __launch_bounds__(256) agg_kernel(
    const float* __restrict__ feat, const float* __restrict__ el, const float* __restrict__ er,
    const float* __restrict__ hin, float* __restrict__ hout,
    const int* __restrict__ rowptr, const int* __restrict__ col,
    const float* __restrict__ b, int n) {
    int gw = (blockIdx.x * blockDim.x + threadIdx.x) >> 5;
    if (gw >= n) return;
    int l = threadIdx.x & 31;
    const int EL = 32 / H;
    int hd = l / EL;
    int li = l & (EL - 1);

    float erv = er[gw * H + hd];
    int start = rowptr[gw], end = rowptr[gw + 1];

    float mx = -3.402823466e38f;
    for (int j = start + li; j < end; j += EL) {
        int s = col[j];
        float e = el[s * H + hd] + erv;
        e = e > 0.f ? e : 0.2f * e;
        mx = fmaxf(mx, e);
    }
#pragma unroll
    for (int off = EL >> 1; off > 0; off >>= 1)
        mx = fmaxf(mx, __shfl_xor_sync(0xffffffffu, mx, off));

    const float4* f4 = (const float4*)feat;
    float4 acc = make_float4(0.f, 0.f, 0.f, 0.f);
    float sw = 0.f;
    int j = start;
    for (; j + 3 < end; j += 4) {
        int s0 = col[j], s1 = col[j + 1], s2 = col[j + 2], s3 = col[j + 3];
        float e0 = el[s0 * H + hd] + erv;
        float e1 = el[s1 * H + hd] + erv;
        float e2 = el[s2 * H + hd] + erv;
        float e3 = el[s3 * H + hd] + erv;
        float4 fa = f4[(size_t)s0 * 32 + l];
        float4 fb = f4[(size_t)s1 * 32 + l];
        float4 fc = f4[(size_t)s2 * 32 + l];
        float4 fd = f4[(size_t)s3 * 32 + l];
        e0 = e0 > 0.f ? e0 : 0.2f * e0;
        e1 = e1 > 0.f ? e1 : 0.2f * e1;
        e2 = e2 > 0.f ? e2 : 0.2f * e2;
        e3 = e3 > 0.f ? e3 : 0.2f * e3;
        float w0 = __expf(e0 - mx), w1 = __expf(e1 - mx);
        float w2 = __expf(e2 - mx), w3 = __expf(e3 - mx);
        sw += (w0 + w1) + (w2 + w3);
        acc.x = fmaf(w0, fa.x, acc.x); acc.y = fmaf(w0, fa.y, acc.y);
        acc.z = fmaf(w0, fa.z, acc.z); acc.w = fmaf(w0, fa.w, acc.w);
        acc.x = fmaf(w1, fb.x, acc.x); acc.y = fmaf(w1, fb.y, acc.y);
        acc.z = fmaf(w1, fb.z, acc.z); acc.w = fmaf(w1, fb.w, acc.w);
        acc.x = fmaf(w2, fc.x, acc.x); acc.y = fmaf(w2, fc.y, acc.y);
        acc.z = fmaf(w2, fc.z, acc.z); acc.w = fmaf(w2, fc.w, acc.w);
        acc.x = fmaf(w3, fd.x, acc.x); acc.y = fmaf(w3, fd.y, acc.y);
        acc.z = fmaf(w3, fd.z, acc.z); acc.w = fmaf(w3, fd.w, acc.w);
    }
    for (; j < end; j++) {
        int s0 = col[j];
        float e0 = el[s0 * H + hd] + erv;
        float4 fa = f4[(size_t)s0 * 32 + l];
        e0 = e0 > 0.f ? e0 : 0.2f * e0;
        float w0 = __expf(e0 - mx);
        sw += w0;
        acc.x = fmaf(w0, fa.x, acc.x); acc.y = fmaf(w0, fa.y, acc.y);
        acc.z = fmaf(w0, fa.z, acc.z); acc.w = fmaf(w0, fa.w, acc.w);
    }

    float inv = sw > 0.f ? 1.0f / sw : 0.f;
    float4 r4 = ((const float4*)hin)[(size_t)gw * 32 + l];
    float4 b4 = ((const float4*)b)[l];
    float4 o;
    o.x = fmaf(acc.x, inv, r4.x + b4.x);
    o.y = fmaf(acc.y, inv, r4.y + b4.y);
    o.z = fmaf(acc.z, inv, r4.z + b4.z);
    o.w = fmaf(acc.w, inv, r4.w + b4.w);
    if (!LAST) {
        o.x = o.x > 0.f ? o.x : expm1f(o.x);
        o.y = o.y > 0.f ? o.y : expm1f(o.y);
        o.z = o.z > 0.f ? o.z : expm1f(o.z);
        o.w = o.w > 0.f ? o.w : expm1f(o.w);
    }
    ((float4*)hout)[(size_t)gw * 32 + l] = o;
}

// ======================= launch =======================
extern "C" void kernel_launch(void* const* d_in, const int* in_sizes, int n_in,
                              void* d_out, int out_size) {
    const float* nf   = (const float*)d_in[0];
    const float* Ws   = (const float*)d_in[1];
    const float* bs   = (const float*)d_in[2];
    const float* al_h = (const float*)d_in[3];
    const float* ar_h = (const float*)d_in[4];
    const float* al_o = (const float*)d_in[5];
    const float* ar_o = (const float*)d_in[6];
    const int*   src  = (const int*)d_in[7];
    const int*   dst  = (const int*)d_in[8];

    int n = in_sizes[0] / 128;
    int E = in_sizes[7];

    void *p_feat, *p_h, *p_el, *p_er, *p_rp, *p_cur, *p_cnt, *p_col, *p_whi, *p_wlo;
    cudaGetSymbolAddress(&p_feat, g_feat);
    cudaGetSymbolAddress(&p_h, g_h);
    cudaGetSymbolAddress(&p_el, g_el);
    cudaGetSymbolAddress(&p_er, g_er);
    cudaGetSymbolAddress(&p_rp, g_rowptr);
    cudaGetSymbolAddress(&p_cur, g_cursor);
    cudaGetSymbolAddress(&p_cnt, g_cnt);
    cudaGetSymbolAddress(&p_col, g_col);
    cudaGetSymbolAddress(&p_whi, g_wt_hi);
    cudaGetSymbolAddress(&p_wlo, g_wt_lo);

    float* feat = (float*)p_feat;
    float* h    = (float*)p_h;
    float* el   = (float*)p_el;
    float* er   = (float*)p_er;
    int*   rp   = (int*)p_rp;
    int*   cur  = (int*)p_cur;
    int*   cnt  = (int*)p_cnt;
    int*   col  = (int*)p_col;
    __nv_bfloat16* whi = (__nv_bfloat16*)p_whi;
    __nv_bfloat16* wlo = (__nv_bfloat16*)p_wlo;

    cudaFuncSetAttribute(mma_gemm_kernel<4>, cudaFuncAttributeMaxDynamicSharedMemorySize, MMA_SMEM);
    cudaFuncSetAttribute(mma_gemm_kernel<1>, cudaFuncAttributeMaxDynamicSharedMemorySize, MMA_SMEM);

    // CSR by dst
    cudaMemsetAsync(cnt, 0, (size_t)n * sizeof(int));
    count_kernel<<<(E + 255) / 256, 256>>>(dst, cnt, E);
    scan_kernel<<<1, 1024>>>(cnt, rp, cur, n);
    scatter_kernel<<<(E + 255) / 256, 256>>>(src, dst, cur, col, E);

    int gb = (n + 127) / 128;
    int ab = (n + 7) / 8;

    // layer 0
    wtrans_kernel<<<64, 256>>>(Ws, whi, wlo);
    mma_gemm_kernel<4><<<gb, 256, MMA_SMEM>>>(nf, whi, wlo, al_h, ar_h, feat, el, er, n);
    agg_kernel<4, false><<<ab, 256>>>(feat, el, er, nf, h, rp, col, bs, n);
    // layers 1, 2
    for (int i = 1; i < 3; i++) {
        wtrans_kernel<<<64, 256>>>(Ws + (size_t)i * 16384, whi, wlo);
        mma_gemm_kernel<4><<<gb, 256, MMA_SMEM>>>(h, whi, wlo, al_h + i * 128, ar_h + i * 128,
                                                  feat, el, er, n);
        agg_kernel<4, false><<<ab, 256>>>(feat, el, er, h, h, rp, col, bs + i * 128, n);
    }
    // layer 3 (1 head) -> out
    wtrans_kernel<<<64, 256>>>(Ws + (size_t)3 * 16384, whi, wlo);
    mma_gemm_kernel<1><<<gb, 256, MMA_SMEM>>>(h, whi, wlo, al_o, ar_o, feat, el, er, n);
    agg_kernel<1, true><<<ab, 256>>>(feat, el, er, h, (float*)d_out, rp, col, bs + 3 * 128, n);
}

// round 4
// speedup vs baseline: 1.3363x; 1.1235x over previous
#include <cuda_runtime.h>
#include <cuda_bf16.h>
#include <cuda_fp16.h>
#include <math.h>
#include <cstdint>

#define NMAX 100000
#define EMAX 1600000

// ======================= scratch (static device globals) =======================
__device__ __align__(16) __half g_feat_h[NMAX * 128];   // fp16 transformed features
__device__ __align__(16) float g_h[NMAX * 128];
__device__ float g_el[NMAX * 4];
__device__ float g_er[NMAX * 4];
__device__ int   g_rowptr[NMAX + 1];
__device__ int   g_cursor[NMAX];
__device__ int   g_cnt[NMAX];
__device__ int   g_col[EMAX];
__device__ __align__(16) __nv_bfloat16 g_wt_hi[4 * 128 * 128];
__device__ __align__(16) __nv_bfloat16 g_wt_lo[4 * 128 * 128];
__device__ int   g_elmax[16];          // [layer][head], order-preserving int encoding

#define ELMAX_INIT ((int)0x80800000)   // encoded -inf

__device__ __forceinline__ int fenc(float f) {
    int i = __float_as_int(f);
    return (i >= 0) ? i : (int)(0x80000000u - (uint32_t)i);
}
__device__ __forceinline__ float fdec(int k) {
    uint32_t u = (k >= 0) ? (uint32_t)k : (uint32_t)(0x80000000u - (uint32_t)k);
    return __uint_as_float(u);
}
__device__ __forceinline__ float leaky(float x) { return x > 0.f ? x : 0.2f * x; }

// ======================= helpers =======================
__device__ __forceinline__ uint32_t smem_u32(const void* p) {
    uint32_t a;
    asm("{ .reg .u64 t; cvta.to.shared.u64 t, %1; cvt.u32.u64 %0, t; }" : "=r"(a) : "l"(p));
    return a;
}
__device__ __forceinline__ void ldm_x4(uint32_t addr, uint32_t& r0, uint32_t& r1,
                                       uint32_t& r2, uint32_t& r3) {
    asm volatile("ldmatrix.sync.aligned.m8n8.x4.shared.b16 {%0,%1,%2,%3}, [%4];"
                 : "=r"(r0), "=r"(r1), "=r"(r2), "=r"(r3) : "r"(addr));
}
__device__ __forceinline__ void mma16816(float* c, const uint32_t* a, const uint32_t* b) {
    asm volatile("mma.sync.aligned.m16n8k16.row.col.f32.bf16.bf16.f32 "
                 "{%0,%1,%2,%3}, {%4,%5,%6,%7}, {%8,%9}, {%0,%1,%2,%3};"
                 : "+f"(c[0]), "+f"(c[1]), "+f"(c[2]), "+f"(c[3])
                 : "r"(a[0]), "r"(a[1]), "r"(a[2]), "r"(a[3]), "r"(b[0]), "r"(b[1]));
}

// ======================= CSR build =======================
__global__ void count_kernel(const int* __restrict__ dst, int* __restrict__ cnt, int E) {
    int i = blockIdx.x * blockDim.x + threadIdx.x;
    if (i < E) atomicAdd(&cnt[dst[i]], 1);
}

__global__ void scan_kernel(const int* __restrict__ cnt, int* __restrict__ rowptr,
                            int* __restrict__ cursor, int n) {
    __shared__ int part[1024];
    int t = threadIdx.x;
    int CH = (n + 1023) >> 10;
    int base = t * CH;
    int s = 0;
    for (int j = 0; j < CH; j++) { int idx = base + j; if (idx < n) s += cnt[idx]; }
    part[t] = s;
    __syncthreads();
    for (int off = 1; off < 1024; off <<= 1) {
        int v = (t >= off) ? part[t - off] : 0;
        __syncthreads();
        part[t] += v;
        __syncthreads();
    }
    int run = (t == 0) ? 0 : part[t - 1];
    for (int j = 0; j < CH; j++) {
        int idx = base + j;
        if (idx < n) { rowptr[idx] = run; cursor[idx] = run; run += cnt[idx]; }
    }
    if (t == 1023) rowptr[n] = part[1023];
}

__global__ void scatter_kernel(const int* __restrict__ src, const int* __restrict__ dst,
                               int* __restrict__ cursor, int* __restrict__ col, int E) {
    int i = blockIdx.x * blockDim.x + threadIdx.x;
    if (i < E) {
        int p = atomicAdd(&cursor[dst[i]], 1);
        col[p] = src[i];
    }
}

// =============== all-layer W transpose + bf16 split + elmax init ===============
__global__ void wtrans_all_kernel(const float* __restrict__ Ws,
                                  __nv_bfloat16* __restrict__ wt_hi,
                                  __nv_bfloat16* __restrict__ wt_lo,
                                  int* __restrict__ elmax) {
    int idx = blockIdx.x * 256 + threadIdx.x;   // 4 * 16384
    if (blockIdx.x == 0 && threadIdx.x < 16) elmax[threadIdx.x] = ELMAX_INIT;
    int layer = idx >> 14;
    int k = (idx >> 7) & 127, nn = idx & 127;
    float v = Ws[idx];                          // Ws[layer][k][n]
    __nv_bfloat16 h = __float2bfloat16(v);
    float lo = v - __bfloat162float(h);
    wt_hi[layer * 16384 + nn * 128 + k] = h;    // Wt[n][k]
    wt_lo[layer * 16384 + nn * 128 + k] = __float2bfloat16(lo);
}

// =============== mma.sync GEMM: feat = h @ W (bf16x3), fused el/er + elmax ===============
// M-tile = 64 rows, N = K = 128. 8 warps: wr = w&1 (row 32-group), wc = w>>1 (col 32-group).
// smem 104448B -> 2 blocks/SM.
#define A_TILE_B (64 * 272)
#define B_TILE_B (128 * 272)
#define OF_AHI 0
#define OF_ALO A_TILE_B
#define OF_BHI (2 * A_TILE_B)
#define OF_BLO (2 * A_TILE_B + B_TILE_B)
#define MMA_SMEM (2 * A_TILE_B + 2 * B_TILE_B)

template <int H>
__global__ void __launch_bounds__(256, 2) mma_gemm_kernel(
    const float* __restrict__ in,
    const __nv_bfloat16* __restrict__ wt_hi, const __nv_bfloat16* __restrict__ wt_lo,
    const float* __restrict__ al, const float* __restrict__ ar,
    __half* __restrict__ feat, float* __restrict__ el, float* __restrict__ er,
    int* __restrict__ elmax, int n) {
    extern __shared__ char sm[];
    const uint32_t sb = smem_u32(sm);
    const int t = threadIdx.x;
    const int row0 = blockIdx.x * 64;

    // ---- stage B = Wt hi/lo (128 rows x 16 chunks) ----
    for (int idx = t; idx < 2048; idx += 256) {
        int r = idx >> 4, c = idx & 15;
        *(uint4*)(sm + OF_BHI + r * 272 + c * 16) = ((const uint4*)wt_hi)[idx];
        *(uint4*)(sm + OF_BLO + r * 272 + c * 16) = ((const uint4*)wt_lo)[idx];
    }
    // ---- stage A (64 rows x 16 chunks): fp32 -> (hi, lo) bf16 ----
    for (int idx = t; idx < 1024; idx += 256) {
        int r = idx >> 4, c = idx & 15;
        int grow = row0 + r;
        float xs[8];
        if (grow < n) {
            const float4* p = (const float4*)(in + (size_t)grow * 128 + c * 8);
            float4 v0 = p[0], v1 = p[1];
            xs[0] = v0.x; xs[1] = v0.y; xs[2] = v0.z; xs[3] = v0.w;
            xs[4] = v1.x; xs[5] = v1.y; xs[6] = v1.z; xs[7] = v1.w;
        } else {
#pragma unroll
            for (int j = 0; j < 8; j++) xs[j] = 0.f;
        }
        union { uint4 u; __nv_bfloat16 b[8]; } uh, ul;
#pragma unroll
        for (int j = 0; j < 8; j++) {
            __nv_bfloat16 hv = __float2bfloat16(xs[j]);
            uh.b[j] = hv;
            ul.b[j] = __float2bfloat16(xs[j] - __bfloat162float(hv));
        }
        *(uint4*)(sm + OF_AHI + r * 272 + c * 16) = uh.u;
        *(uint4*)(sm + OF_ALO + r * 272 + c * 16) = ul.u;
    }
    __syncthreads();

    const int l = t & 31, w = t >> 5;
    const int wr = w & 1, wc = w >> 1;     // rows 32*wr, cols 32*wc

    const uint32_t a_lane = (uint32_t)((l & 15) * 272 + ((l >= 16) ? 16 : 0));
    const uint32_t b_lane = (uint32_t)(((l & 7) + ((l >= 16) ? 8 : 0)) * 272 + (((l & 15) >= 8) ? 16 : 0));

    float acc[2][4][4];
#pragma unroll
    for (int mi = 0; mi < 2; mi++)
#pragma unroll
        for (int nj = 0; nj < 4; nj++)
#pragma unroll
            for (int q = 0; q < 4; q++) acc[mi][nj][q] = 0.f;

#pragma unroll
    for (int p = 0; p < 3; p++) {
        const uint32_t abase = sb + ((p == 2) ? OF_ALO : OF_AHI) + (uint32_t)(wr * 32) * 272 + a_lane;
        const uint32_t bbase = sb + ((p == 1) ? OF_BLO : OF_BHI) + (uint32_t)(wc * 32) * 272 + b_lane;
#pragma unroll
        for (int ks = 0; ks < 8; ks++) {
            uint32_t a[2][4];
            ldm_x4(abase + ks * 32,            a[0][0], a[0][1], a[0][2], a[0][3]);
            ldm_x4(abase + 16 * 272 + ks * 32, a[1][0], a[1][1], a[1][2], a[1][3]);
            uint32_t b[4][2];
            {
                uint32_t r0, r1, r2, r3;
                ldm_x4(bbase + ks * 32, r0, r1, r2, r3);
                b[0][0] = r0; b[0][1] = r1; b[1][0] = r2; b[1][1] = r3;
                ldm_x4(bbase + 16 * 272 + ks * 32, r0, r1, r2, r3);
                b[2][0] = r0; b[2][1] = r1; b[3][0] = r2; b[3][1] = r3;
            }
#pragma unroll
            for (int mi = 0; mi < 2; mi++)
#pragma unroll
                for (int nj = 0; nj < 4; nj++) mma16816(acc[mi][nj], a[mi], b[nj]);
        }
    }

    __syncthreads();   // tiles dead; reuse smem for H==1 partials

    float* elp = (float*)sm;               // [4][64]
    float* erp = elp + 256;
    const int q = l >> 2, qq = l & 3;

    float pelv[4], perv[4];                // per (mi, rh)
#pragma unroll
    for (int mi = 0; mi < 2; mi++) {
#pragma unroll
        for (int rh = 0; rh < 2; rh++) {
            int lrow = wr * 32 + mi * 16 + rh * 8 + q;
            int row = row0 + lrow;
            float pel = 0.f, per = 0.f;
#pragma unroll
            for (int nj = 0; nj < 4; nj++) {
                float v0 = acc[mi][nj][rh * 2 + 0];
                float v1 = acc[mi][nj][rh * 2 + 1];
                int colg = wc * 32 + nj * 8 + qq * 2;
                if (row < n)
                    *(__half2*)(feat + (size_t)row * 128 + colg) = __floats2half2_rn(v0, v1);
                pel = fmaf(v0, __ldg(al + colg), pel);
                pel = fmaf(v1, __ldg(al + colg + 1), pel);
                per = fmaf(v0, __ldg(ar + colg), per);
                per = fmaf(v1, __ldg(ar + colg + 1), per);
            }
            pel += __shfl_xor_sync(0xffffffffu, pel, 1);
            pel += __shfl_xor_sync(0xffffffffu, pel, 2);
            per += __shfl_xor_sync(0xffffffffu, per, 1);
            per += __shfl_xor_sync(0xffffffffu, per, 2);
            if (H == 4) {
                if (qq == 0 && row < n) {
                    el[row * 4 + wc] = pel;
                    er[row * 4 + wc] = per;
                }
            } else {
                if (qq == 0) {
                    elp[wc * 64 + lrow] = pel;
                    erp[wc * 64 + lrow] = per;
                }
            }
            int idx = mi * 2 + rh;
            pelv[idx] = (row < n) ? pel : -3.402823466e38f;
            perv[idx] = per;
            (void)perv;
        }
    }

    if (H == 4) {
        // per-warp max of el for this head -> 1 atomic per warp
        float m = fmaxf(fmaxf(pelv[0], pelv[1]), fmaxf(pelv[2], pelv[3]));
#pragma unroll
        for (int off = 16; off > 0; off >>= 1)
            m = fmaxf(m, __shfl_xor_sync(0xffffffffu, m, off));
        if (l == 0) atomicMax(&elmax[wc], fenc(m));
    } else {
        __syncthreads();
        if (t < 64) {
            int row = row0 + t;
            float se = elp[t] + elp[64 + t] + elp[128 + t] + elp[192 + t];
            float sr = erp[t] + erp[64 + t] + erp[128 + t] + erp[192 + t];
            float m = -3.402823466e38f;
            if (row < n) {
                el[row] = se;
                er[row] = sr;
                m = se;
            }
#pragma unroll
            for (int off = 16; off > 0; off >>= 1)
                m = fmaxf(m, __shfl_xor_sync(0xffffffffu, m, off));
            if ((t & 31) == 0) atomicMax(&elmax[0], fenc(m));
        }
    }
}

// =============== aggregation: single-pass softmax-gather, warp per node ===============
template <int H, bool LAST>
__global__ void __launch_bounds__(256) agg_kernel(
    const __half* __restrict__ feat, const float* __restrict__ el, const float* __restrict__ er,
    const int* __restrict__ elmax,
    const float* __restrict__ hin, float* __restrict__ hout,
    const int* __restrict__ rowptr, const int* __restrict__ col,
    const float* __restrict__ b, int n) {
    int gw = (blockIdx.x * blockDim.x + threadIdx.x) >> 5;
    if (gw >= n) return;
    int l = threadIdx.x & 31;
    int hd = (H == 4) ? (l >> 3) : 0;

    float erv = er[gw * H + hd];
    float c = leaky(fdec(__ldg(&elmax[hd])) + erv);   // upper bound on all edge logits
    int start = rowptr[gw], end = rowptr[gw + 1];

    const uint2* f2 = (const uint2*)feat;             // lane l -> cols 4l..4l+3
    float4 acc = make_float4(0.f, 0.f, 0.f, 0.f);
    float sw = 0.f;
    int j = start;
    for (; j + 3 < end; j += 4) {
        int s0 = col[j], s1 = col[j + 1], s2 = col[j + 2], s3 = col[j + 3];
        float e0 = el[s0 * H + hd] + erv;
        float e1 = el[s1 * H + hd] + erv;
        float e2 = el[s2 * H + hd] + erv;
        float e3 = el[s3 * H + hd] + erv;
        uint2 fa = f2[(size_t)s0 * 32 + l];
        uint2 fb = f2[(size_t)s1 * 32 + l];
        uint2 fc = f2[(size_t)s2 * 32 + l];
        uint2 fd = f2[(size_t)s3 * 32 + l];
        float w0 = __expf(leaky(e0) - c), w1 = __expf(leaky(e1) - c);
        float w2 = __expf(leaky(e2) - c), w3 = __expf(leaky(e3) - c);
        sw += (w0 + w1) + (w2 + w3);
        float2 a0 = __half22float2(*(const __half2*)&fa.x);
        float2 a1 = __half22float2(*(const __half2*)&fa.y);
        float2 b0 = __half22float2(*(const __half2*)&fb.x);
        float2 b1 = __half22float2(*(const __half2*)&fb.y);
        float2 c0 = __half22float2(*(const __half2*)&fc.x);
        float2 c1 = __half22float2(*(const __half2*)&fc.y);
        float2 d0 = __half22float2(*(const __half2*)&fd.x);
        float2 d1 = __half22float2(*(const __half2*)&fd.y);
        acc.x = fmaf(w0, a0.x, acc.x); acc.y = fmaf(w0, a0.y, acc.y);
        acc.z = fmaf(w0, a1.x, acc.z); acc.w = fmaf(w0, a1.y, acc.w);
        acc.x = fmaf(w1, b0.x, acc.x); acc.y = fmaf(w1, b0.y, acc.y);
        acc.z = fmaf(w1, b1.x, acc.z); acc.w = fmaf(w1, b1.y, acc.w);
        acc.x = fmaf(w2, c0.x, acc.x); acc.y = fmaf(w2, c0.y, acc.y);
        acc.z = fmaf(w2, c1.x, acc.z); acc.w = fmaf(w2, c1.y, acc.w);
        acc.x = fmaf(w3, d0.x, acc.x); acc.y = fmaf(w3, d0.y, acc.y);
        acc.z = fmaf(w3, d1.x, acc.z); acc.w = fmaf(w3, d1.y, acc.w);
    }
    for (; j < end; j++) {
        int s0 = col[j];
        float e0 = el[s0 * H + hd] + erv;
        uint2 fa = f2[(size_t)s0 * 32 + l];
        float w0 = __expf(leaky(e0) - c);
        sw += w0;
        float2 a0 = __half22float2(*(const __half2*)&fa.x);
        float2 a1 = __half22float2(*(const __half2*)&fa.y);
        acc.x = fmaf(w0, a0.x, acc.x); acc.y = fmaf(w0, a0.y, acc.y);
        acc.z = fmaf(w0, a1.x, acc.z); acc.w = fmaf(w0, a1.y, acc.w);
    }

    float inv = sw > 0.f ? 1.0f / sw : 0.f;
    float4 r4 = ((const float4*)hin)[(size_t)gw * 32 + l];
    float4 b4 = ((const float4*)b)[l];
    float4 o;
    o.x = fmaf(acc.x, inv, r4.x + b4.x);
    o.y = fmaf(acc.y, inv, r4.y + b4.y);
    o.z = fmaf(acc.z, inv, r4.z + b4.z);
    o.w = fmaf(acc.w, inv, r4.w + b4.w);
    if (!LAST) {
        o.x = o.x > 0.f ? o.x : expm1f(o.x);
        o.y = o.y > 0.f ? o.y : expm1f(o.y);
        o.z = o.z > 0.f ? o.z : expm1f(o.z);
        o.w = o.w > 0.f ? o.w : expm1f(o.w);
    }
    ((float4*)hout)[(size_t)gw * 32 + l] = o;
}

// ======================= launch =======================
extern "C" void kernel_launch(void* const* d_in, const int* in_sizes, int n_in,
                              void* d_out, int out_size) {
    const float* nf   = (const float*)d_in[0];
    const float* Ws   = (const float*)d_in[1];
    const float* bs   = (const float*)d_in[2];
    const float* al_h = (const float*)d_in[3];
    const float* ar_h = (const float*)d_in[4];
    const float* al_o = (const float*)d_in[5];
    const float* ar_o = (const float*)d_in[6];
    const int*   src  = (const int*)d_in[7];
    const int*   dst  = (const int*)d_in[8];

    int n = in_sizes[0] / 128;
    int E = in_sizes[7];

    void *p_feat, *p_h, *p_el, *p_er, *p_rp, *p_cur, *p_cnt, *p_col, *p_whi, *p_wlo, *p_em;
    cudaGetSymbolAddress(&p_feat, g_feat_h);
    cudaGetSymbolAddress(&p_h, g_h);
    cudaGetSymbolAddress(&p_el, g_el);
    cudaGetSymbolAddress(&p_er, g_er);
    cudaGetSymbolAddress(&p_rp, g_rowptr);
    cudaGetSymbolAddress(&p_cur, g_cursor);
    cudaGetSymbolAddress(&p_cnt, g_cnt);
    cudaGetSymbolAddress(&p_col, g_col);
    cudaGetSymbolAddress(&p_whi, g_wt_hi);
    cudaGetSymbolAddress(&p_wlo, g_wt_lo);
    cudaGetSymbolAddress(&p_em, g_elmax);

    __half* feat = (__half*)p_feat;
    float* h    = (float*)p_h;
    float* el   = (float*)p_el;
    float* er   = (float*)p_er;
    int*   rp   = (int*)p_rp;
    int*   cur  = (int*)p_cur;
    int*   cnt  = (int*)p_cnt;
    int*   col  = (int*)p_col;
    __nv_bfloat16* whi = (__nv_bfloat16*)p_whi;
    __nv_bfloat16* wlo = (__nv_bfloat16*)p_wlo;
    int* em = (int*)p_em;

    cudaFuncSetAttribute(mma_gemm_kernel<4>, cudaFuncAttributeMaxDynamicSharedMemorySize, MMA_SMEM);
    cudaFuncSetAttribute(mma_gemm_kernel<1>, cudaFuncAttributeMaxDynamicSharedMemorySize, MMA_SMEM);

    // CSR by dst + all-layer weight prep
    cudaMemsetAsync(cnt, 0, (size_t)n * sizeof(int));
    count_kernel<<<(E + 255) / 256, 256>>>(dst, cnt, E);
    scan_kernel<<<1, 1024>>>(cnt, rp, cur, n);
    scatter_kernel<<<(E + 255) / 256, 256>>>(src, dst, cur, col, E);
    wtrans_all_kernel<<<256, 256>>>(Ws, whi, wlo, em);

    int gb = (n + 63) / 64;
    int ab = (n + 7) / 8;

    // layer 0
    mma_gemm_kernel<4><<<gb, 256, MMA_SMEM>>>(nf, whi, wlo, al_h, ar_h, feat, el, er, em, n);
    agg_kernel<4, false><<<ab, 256>>>(feat, el, er, em, nf, h, rp, col, bs, n);
    // layers 1, 2
    for (int i = 1; i < 3; i++) {
        mma_gemm_kernel<4><<<gb, 256, MMA_SMEM>>>(h, whi + (size_t)i * 16384, wlo + (size_t)i * 16384,
                                                  al_h + i * 128, ar_h + i * 128,
                                                  feat, el, er, em + i * 4, n);
        agg_kernel<4, false><<<ab, 256>>>(feat, el, er, em + i * 4, h, h, rp, col, bs + i * 128, n);
    }
    // layer 3 (1 head) -> out
    mma_gemm_kernel<1><<<gb, 256, MMA_SMEM>>>(h, whi + (size_t)3 * 16384, wlo + (size_t)3 * 16384,
                                              al_o, ar_o, feat, el, er, em + 12, n);
    agg_kernel<1, true><<<ab, 256>>>(feat, el, er, em + 12, h, (float*)d_out, rp, col, bs + 3 * 128, n);
}

// round 5
// speedup vs baseline: 1.3536x; 1.0129x over previous
#include <cuda_runtime.h>
#include <cuda_bf16.h>
#include <cuda_fp16.h>
#include <math.h>
#include <cstdint>

#define NMAX 100000
#define EMAX 1600000

// ======================= scratch (static device globals) =======================
__device__ __align__(16) __half g_feat_h[NMAX * 128];   // fp16 transformed features
__device__ __align__(16) float g_h[NMAX * 128];
__device__ float g_el[NMAX * 4];
__device__ float g_er[NMAX * 4];
__device__ int   g_rowptr[NMAX + 1];
__device__ int   g_cursor[NMAX];
__device__ int   g_cnt[NMAX];
__device__ int   g_col[EMAX];
__device__ __align__(16) __nv_bfloat16 g_wt_hi[4 * 128 * 128];
__device__ __align__(16) __nv_bfloat16 g_wt_lo[4 * 128 * 128];
__device__ int   g_elmax[16];          // [layer][head], order-preserving int encoding

#define ELMAX_INIT ((int)0x80800000)   // encoded -inf

__device__ __forceinline__ int fenc(float f) {
    int i = __float_as_int(f);
    return (i >= 0) ? i : (int)(0x80000000u - (uint32_t)i);
}
__device__ __forceinline__ float fdec(int k) {
    uint32_t u = (k >= 0) ? (uint32_t)k : (uint32_t)(0x80000000u - (uint32_t)k);
    return __uint_as_float(u);
}
__device__ __forceinline__ float leaky(float x) { return x > 0.f ? x : 0.2f * x; }

// ======================= helpers =======================
__device__ __forceinline__ uint32_t smem_u32(const void* p) {
    uint32_t a;
    asm("{ .reg .u64 t; cvta.to.shared.u64 t, %1; cvt.u32.u64 %0, t; }" : "=r"(a) : "l"(p));
    return a;
}
__device__ __forceinline__ void ldm_x4(uint32_t addr, uint32_t& r0, uint32_t& r1,
                                       uint32_t& r2, uint32_t& r3) {
    asm volatile("ldmatrix.sync.aligned.m8n8.x4.shared.b16 {%0,%1,%2,%3}, [%4];"
                 : "=r"(r0), "=r"(r1), "=r"(r2), "=r"(r3) : "r"(addr));
}
__device__ __forceinline__ void mma16816(float* c, const uint32_t* a, const uint32_t* b) {
    asm volatile("mma.sync.aligned.m16n8k16.row.col.f32.bf16.bf16.f32 "
                 "{%0,%1,%2,%3}, {%4,%5,%6,%7}, {%8,%9}, {%0,%1,%2,%3};"
                 : "+f"(c[0]), "+f"(c[1]), "+f"(c[2]), "+f"(c[3])
                 : "r"(a[0]), "r"(a[1]), "r"(a[2]), "r"(a[3]), "r"(b[0]), "r"(b[1]));
}

// ======================= CSR build =======================
__global__ void count_kernel(const int* __restrict__ dst, int* __restrict__ cnt, int E) {
    int i = blockIdx.x * blockDim.x + threadIdx.x;
    if (i < E) atomicAdd(&cnt[dst[i]], 1);
}

__global__ void scan_kernel(const int* __restrict__ cnt, int* __restrict__ rowptr,
                            int* __restrict__ cursor, int n) {
    __shared__ int part[1024];
    int t = threadIdx.x;
    int CH = (n + 1023) >> 10;
    int base = t * CH;
    int s = 0;
    for (int j = 0; j < CH; j++) { int idx = base + j; if (idx < n) s += cnt[idx]; }
    part[t] = s;
    __syncthreads();
    for (int off = 1; off < 1024; off <<= 1) {
        int v = (t >= off) ? part[t - off] : 0;
        __syncthreads();
        part[t] += v;
        __syncthreads();
    }
    int run = (t == 0) ? 0 : part[t - 1];
    for (int j = 0; j < CH; j++) {
        int idx = base + j;
        if (idx < n) { rowptr[idx] = run; cursor[idx] = run; run += cnt[idx]; }
    }
    if (t == 1023) rowptr[n] = part[1023];
}

__global__ void scatter_kernel(const int* __restrict__ src, const int* __restrict__ dst,
                               int* __restrict__ cursor, int* __restrict__ col, int E) {
    int i = blockIdx.x * blockDim.x + threadIdx.x;
    if (i < E) {
        int p = atomicAdd(&cursor[dst[i]], 1);
        col[p] = src[i];
    }
}

// =============== all-layer W transpose + bf16 split + elmax init ===============
__global__ void wtrans_all_kernel(const float* __restrict__ Ws,
                                  __nv_bfloat16* __restrict__ wt_hi,
                                  __nv_bfloat16* __restrict__ wt_lo,
                                  int* __restrict__ elmax) {
    int idx = blockIdx.x * 256 + threadIdx.x;   // 4 * 16384
    if (blockIdx.x == 0 && threadIdx.x < 16) elmax[threadIdx.x] = ELMAX_INIT;
    int layer = idx >> 14;
    int k = (idx >> 7) & 127, nn = idx & 127;
    float v = Ws[idx];                          // Ws[layer][k][n]
    __nv_bfloat16 h = __float2bfloat16(v);
    float lo = v - __bfloat162float(h);
    wt_hi[layer * 16384 + nn * 128 + k] = h;    // Wt[n][k]
    wt_lo[layer * 16384 + nn * 128 + k] = __float2bfloat16(lo);
}

// =============== persistent mma.sync GEMM: feat = h @ W (bf16x3), fused el/er ===============
// Persistent blocks: B (W hi/lo) staged ONCE per block, A restaged per 64-row tile.
#define A_TILE_B (64 * 272)
#define B_TILE_B (128 * 272)
#define OF_AHI 0
#define OF_ALO A_TILE_B
#define OF_BHI (2 * A_TILE_B)
#define OF_BLO (2 * A_TILE_B + B_TILE_B)
#define MMA_SMEM (2 * A_TILE_B + 2 * B_TILE_B)
#define GEMM_GRID 296

template <int H>
__global__ void __launch_bounds__(256, 2) mma_gemm_kernel(
    const float* __restrict__ in,
    const __nv_bfloat16* __restrict__ wt_hi, const __nv_bfloat16* __restrict__ wt_lo,
    const float* __restrict__ al, const float* __restrict__ ar,
    __half* __restrict__ feat, float* __restrict__ el, float* __restrict__ er,
    int* __restrict__ elmax, int n) {
    extern __shared__ char sm[];
    const uint32_t sb = smem_u32(sm);
    const int t = threadIdx.x;
    const int ntiles = (n + 63) >> 6;

    // ---- stage B = Wt hi/lo once ----
    for (int idx = t; idx < 2048; idx += 256) {
        int r = idx >> 4, c = idx & 15;
        *(uint4*)(sm + OF_BHI + r * 272 + c * 16) = ((const uint4*)wt_hi)[idx];
        *(uint4*)(sm + OF_BLO + r * 272 + c * 16) = ((const uint4*)wt_lo)[idx];
    }

    const int l = t & 31, w = t >> 5;
    const int wr = w & 1, wc = w >> 1;     // rows 32*wr, cols 32*wc
    const uint32_t a_lane = (uint32_t)((l & 15) * 272 + ((l >= 16) ? 16 : 0));
    const uint32_t b_lane = (uint32_t)(((l & 7) + ((l >= 16) ? 8 : 0)) * 272 + (((l & 15) >= 8) ? 16 : 0));
    const int q = l >> 2, qq = l & 3;
    float* elp = (float*)sm;               // [4][64] (aliases A region; synced)
    float* erp = elp + 256;

    for (int tile = blockIdx.x; tile < ntiles; tile += gridDim.x) {
        const int row0 = tile * 64;
        __syncthreads();   // previous iteration fully done (elp reads / ldmatrix)

        // ---- stage A (64 rows): fp32 -> (hi, lo) bf16 ----
        for (int idx = t; idx < 1024; idx += 256) {
            int r = idx >> 4, c = idx & 15;
            int grow = row0 + r;
            float xs[8];
            if (grow < n) {
                const float4* p = (const float4*)(in + (size_t)grow * 128 + c * 8);
                float4 v0 = p[0], v1 = p[1];
                xs[0] = v0.x; xs[1] = v0.y; xs[2] = v0.z; xs[3] = v0.w;
                xs[4] = v1.x; xs[5] = v1.y; xs[6] = v1.z; xs[7] = v1.w;
            } else {
#pragma unroll
                for (int j = 0; j < 8; j++) xs[j] = 0.f;
            }
            union { uint4 u; __nv_bfloat16 b[8]; } uh, ul;
#pragma unroll
            for (int j = 0; j < 8; j++) {
                __nv_bfloat16 hv = __float2bfloat16(xs[j]);
                uh.b[j] = hv;
                ul.b[j] = __float2bfloat16(xs[j] - __bfloat162float(hv));
            }
            *(uint4*)(sm + OF_AHI + r * 272 + c * 16) = uh.u;
            *(uint4*)(sm + OF_ALO + r * 272 + c * 16) = ul.u;
        }
        __syncthreads();

        float acc[2][4][4];
#pragma unroll
        for (int mi = 0; mi < 2; mi++)
#pragma unroll
            for (int nj = 0; nj < 4; nj++)
#pragma unroll
                for (int qk = 0; qk < 4; qk++) acc[mi][nj][qk] = 0.f;

#pragma unroll
        for (int p = 0; p < 3; p++) {
            const uint32_t abase = sb + ((p == 2) ? OF_ALO : OF_AHI) + (uint32_t)(wr * 32) * 272 + a_lane;
            const uint32_t bbase = sb + ((p == 1) ? OF_BLO : OF_BHI) + (uint32_t)(wc * 32) * 272 + b_lane;
#pragma unroll
            for (int ks = 0; ks < 8; ks++) {
                uint32_t a[2][4];
                ldm_x4(abase + ks * 32,            a[0][0], a[0][1], a[0][2], a[0][3]);
                ldm_x4(abase + 16 * 272 + ks * 32, a[1][0], a[1][1], a[1][2], a[1][3]);
                uint32_t b[4][2];
                {
                    uint32_t r0, r1, r2, r3;
                    ldm_x4(bbase + ks * 32, r0, r1, r2, r3);
                    b[0][0] = r0; b[0][1] = r1; b[1][0] = r2; b[1][1] = r3;
                    ldm_x4(bbase + 16 * 272 + ks * 32, r0, r1, r2, r3);
                    b[2][0] = r0; b[2][1] = r1; b[3][0] = r2; b[3][1] = r3;
                }
#pragma unroll
                for (int mi = 0; mi < 2; mi++)
#pragma unroll
                    for (int nj = 0; nj < 4; nj++) mma16816(acc[mi][nj], a[mi], b[nj]);
            }
        }

        __syncthreads();   // A tile dead; elp region reusable (H==1)

        float pelv[4];
#pragma unroll
        for (int mi = 0; mi < 2; mi++) {
#pragma unroll
            for (int rh = 0; rh < 2; rh++) {
                int lrow = wr * 32 + mi * 16 + rh * 8 + q;
                int row = row0 + lrow;
                float pel = 0.f, per = 0.f;
#pragma unroll
                for (int nj = 0; nj < 4; nj++) {
                    float v0 = acc[mi][nj][rh * 2 + 0];
                    float v1 = acc[mi][nj][rh * 2 + 1];
                    int colg = wc * 32 + nj * 8 + qq * 2;
                    if (row < n)
                        *(__half2*)(feat + (size_t)row * 128 + colg) = __floats2half2_rn(v0, v1);
                    pel = fmaf(v0, __ldg(al + colg), pel);
                    pel = fmaf(v1, __ldg(al + colg + 1), pel);
                    per = fmaf(v0, __ldg(ar + colg), per);
                    per = fmaf(v1, __ldg(ar + colg + 1), per);
                }
                pel += __shfl_xor_sync(0xffffffffu, pel, 1);
                pel += __shfl_xor_sync(0xffffffffu, pel, 2);
                per += __shfl_xor_sync(0xffffffffu, per, 1);
                per += __shfl_xor_sync(0xffffffffu, per, 2);
                if (H == 4) {
                    if (qq == 0 && row < n) {
                        el[row * 4 + wc] = pel;
                        er[row * 4 + wc] = per;
                    }
                } else {
                    if (qq == 0) {
                        elp[wc * 64 + lrow] = pel;
                        erp[wc * 64 + lrow] = per;
                    }
                }
                pelv[mi * 2 + rh] = (row < n) ? pel : -3.402823466e38f;
                (void)per;
            }
        }

        if (H == 4) {
            float m = fmaxf(fmaxf(pelv[0], pelv[1]), fmaxf(pelv[2], pelv[3]));
#pragma unroll
            for (int off = 16; off > 0; off >>= 1)
                m = fmaxf(m, __shfl_xor_sync(0xffffffffu, m, off));
            if (l == 0) atomicMax(&elmax[wc], fenc(m));
        } else {
            __syncthreads();
            if (t < 64) {
                int row = row0 + t;
                float se = elp[t] + elp[64 + t] + elp[128 + t] + elp[192 + t];
                float sr = erp[t] + erp[64 + t] + erp[128 + t] + erp[192 + t];
                float m = -3.402823466e38f;
                if (row < n) {
                    el[row] = se;
                    er[row] = sr;
                    m = se;
                }
#pragma unroll
                for (int off = 16; off > 0; off >>= 1)
                    m = fmaxf(m, __shfl_xor_sync(0xffffffffu, m, off));
                if ((t & 31) == 0) atomicMax(&elmax[0], fenc(m));
            }
        }
    }
}

// =============== aggregation: single-pass softmax-gather, warp per node, unroll 8 ===============
template <int H, bool LAST>
__global__ void __launch_bounds__(256) agg_kernel(
    const __half* __restrict__ feat, const float* __restrict__ el, const float* __restrict__ er,
    const int* __restrict__ elmax,
    const float* __restrict__ hin, float* __restrict__ hout,
    const int* __restrict__ rowptr, const int* __restrict__ col,
    const float* __restrict__ b, int n) {
    int gw = (blockIdx.x * blockDim.x + threadIdx.x) >> 5;
    if (gw >= n) return;
    int l = threadIdx.x & 31;
    int hd = (H == 4) ? (l >> 3) : 0;

    float erv = er[gw * H + hd];
    float c = leaky(fdec(__ldg(&elmax[hd])) + erv);   // upper bound on all edge logits
    int start = rowptr[gw], end = rowptr[gw + 1];

    const uint2* f2 = (const uint2*)feat;             // lane l -> cols 4l..4l+3
    float4 acc = make_float4(0.f, 0.f, 0.f, 0.f);
    float sw = 0.f;
    int j = start;
    for (; j + 7 < end; j += 8) {
        int s[8];
#pragma unroll
        for (int k = 0; k < 8; k++) s[k] = __ldg(col + j + k);
        float ev[8];
#pragma unroll
        for (int k = 0; k < 8; k++) ev[k] = __ldg(el + s[k] * H + hd);
        uint2 f[8];
#pragma unroll
        for (int k = 0; k < 8; k++) f[k] = f2[(size_t)s[k] * 32 + l];
#pragma unroll
        for (int k = 0; k < 8; k++) {
            float wk = __expf(leaky(ev[k] + erv) - c);
            sw += wk;
            float2 p0 = __half22float2(*(const __half2*)&f[k].x);
            float2 p1 = __half22float2(*(const __half2*)&f[k].y);
            acc.x = fmaf(wk, p0.x, acc.x); acc.y = fmaf(wk, p0.y, acc.y);
            acc.z = fmaf(wk, p1.x, acc.z); acc.w = fmaf(wk, p1.y, acc.w);
        }
    }
    for (; j < end; j++) {
        int s0 = __ldg(col + j);
        float e0 = __ldg(el + s0 * H + hd) + erv;
        uint2 fa = f2[(size_t)s0 * 32 + l];
        float w0 = __expf(leaky(e0) - c);
        sw += w0;
        float2 p0 = __half22float2(*(const __half2*)&fa.x);
        float2 p1 = __half22float2(*(const __half2*)&fa.y);
        acc.x = fmaf(w0, p0.x, acc.x); acc.y = fmaf(w0, p0.y, acc.y);
        acc.z = fmaf(w0, p1.x, acc.z); acc.w = fmaf(w0, p1.y, acc.w);
    }

    float inv = sw > 0.f ? 1.0f / sw : 0.f;
    float4 r4 = ((const float4*)hin)[(size_t)gw * 32 + l];
    float4 b4 = ((const float4*)b)[l];
    float4 o;
    o.x = fmaf(acc.x, inv, r4.x + b4.x);
    o.y = fmaf(acc.y, inv, r4.y + b4.y);
    o.z = fmaf(acc.z, inv, r4.z + b4.z);
    o.w = fmaf(acc.w, inv, r4.w + b4.w);
    if (!LAST) {
        o.x = o.x > 0.f ? o.x : expm1f(o.x);
        o.y = o.y > 0.f ? o.y : expm1f(o.y);
        o.z = o.z > 0.f ? o.z : expm1f(o.z);
        o.w = o.w > 0.f ? o.w : expm1f(o.w);
    }
    ((float4*)hout)[(size_t)gw * 32 + l] = o;
}

// ======================= launch =======================
extern "C" void kernel_launch(void* const* d_in, const int* in_sizes, int n_in,
                              void* d_out, int out_size) {
    const float* nf   = (const float*)d_in[0];
    const float* Ws   = (const float*)d_in[1];
    const float* bs   = (const float*)d_in[2];
    const float* al_h = (const float*)d_in[3];
    const float* ar_h = (const float*)d_in[4];
    const float* al_o = (const float*)d_in[5];
    const float* ar_o = (const float*)d_in[6];
    const int*   src  = (const int*)d_in[7];
    const int*   dst  = (const int*)d_in[8];

    int n = in_sizes[0] / 128;
    int E = in_sizes[7];

    void *p_feat, *p_h, *p_el, *p_er, *p_rp, *p_cur, *p_cnt, *p_col, *p_whi, *p_wlo, *p_em;
    cudaGetSymbolAddress(&p_feat, g_feat_h);
    cudaGetSymbolAddress(&p_h, g_h);
    cudaGetSymbolAddress(&p_el, g_el);
    cudaGetSymbolAddress(&p_er, g_er);
    cudaGetSymbolAddress(&p_rp, g_rowptr);
    cudaGetSymbolAddress(&p_cur, g_cursor);
    cudaGetSymbolAddress(&p_cnt, g_cnt);
    cudaGetSymbolAddress(&p_col, g_col);
    cudaGetSymbolAddress(&p_whi, g_wt_hi);
    cudaGetSymbolAddress(&p_wlo, g_wt_lo);
    cudaGetSymbolAddress(&p_em, g_elmax);

    __half* feat = (__half*)p_feat;
    float* h    = (float*)p_h;
    float* el   = (float*)p_el;
    float* er   = (float*)p_er;
    int*   rp   = (int*)p_rp;
    int*   cur  = (int*)p_cur;
    int*   cnt  = (int*)p_cnt;
    int*   col  = (int*)p_col;
    __nv_bfloat16* whi = (__nv_bfloat16*)p_whi;
    __nv_bfloat16* wlo = (__nv_bfloat16*)p_wlo;
    int* em = (int*)p_em;

    cudaFuncSetAttribute(mma_gemm_kernel<4>, cudaFuncAttributeMaxDynamicSharedMemorySize, MMA_SMEM);
    cudaFuncSetAttribute(mma_gemm_kernel<1>, cudaFuncAttributeMaxDynamicSharedMemorySize, MMA_SMEM);

    // CSR by dst + all-layer weight prep
    cudaMemsetAsync(cnt, 0, (size_t)n * sizeof(int));
    count_kernel<<<(E + 255) / 256, 256>>>(dst, cnt, E);
    scan_kernel<<<1, 1024>>>(cnt, rp, cur, n);
    scatter_kernel<<<(E + 255) / 256, 256>>>(src, dst, cur, col, E);
    wtrans_all_kernel<<<256, 256>>>(Ws, whi, wlo, em);

    int ab = (n + 7) / 8;

    // layer 0
    mma_gemm_kernel<4><<<GEMM_GRID, 256, MMA_SMEM>>>(nf, whi, wlo, al_h, ar_h, feat, el, er, em, n);
    agg_kernel<4, false><<<ab, 256>>>(feat, el, er, em, nf, h, rp, col, bs, n);
    // layers 1, 2
    for (int i = 1; i < 3; i++) {
        mma_gemm_kernel<4><<<GEMM_GRID, 256, MMA_SMEM>>>(h, whi + (size_t)i * 16384, wlo + (size_t)i * 16384,
                                                         al_h + i * 128, ar_h + i * 128,
                                                         feat, el, er, em + i * 4, n);
        agg_kernel<4, false><<<ab, 256>>>(feat, el, er, em + i * 4, h, h, rp, col, bs + i * 128, n);
    }
    // layer 3 (1 head) -> out
    mma_gemm_kernel<1><<<GEMM_GRID, 256, MMA_SMEM>>>(h, whi + (size_t)3 * 16384, wlo + (size_t)3 * 16384,
                                                     al_o, ar_o, feat, el, er, em + 12, n);
    agg_kernel<1, true><<<ab, 256>>>(feat, el, er, em + 12, h, (float*)d_out, rp, col, bs + 3 * 128, n);
}